// round 9
// baseline (speedup 1.0000x reference)
#include <cuda_runtime.h>
#include <cuda_bf16.h>
#include <cstdint>

#define M_DIM 8192
#define K_DIM 4096
#define N_DIM 16384

#define BM 128
#define BN 128
#define BKE 64                     // K elements per stage (bf16) = 128B rows
#define NKT (K_DIM / BKE)          // 64
#define NS 3
#define STG_A (BM * 128)           // 16384 bytes
#define STG_B (BN * 128)           // 16384 bytes
#define STG (STG_A + STG_B)        // 32768
#define SMEM_TOTAL (NS * STG + 1024 + 128)
#define TILES_TOTAL ((M_DIM / BM) * (N_DIM / BN))   // 8192

// Tiled, pre-swizzled bf16 operand images (device globals; allocation-free rule)
static __device__ __align__(128) __nv_bfloat16 g_qa[(size_t)M_DIM * K_DIM];  // 64 MB
static __device__ __align__(128) __nv_bfloat16 g_wb[(size_t)N_DIM * K_DIM];  // 128 MB
static __device__ float g_sx[M_DIM];

// ---------------------------------------------------------------------------
// Kernel 1: per-row absmax + int8 quantization -> bf16 (exact for |q|<=127),
// tile-major swizzled image: g_qa blocks [tm][kt], 128 rows x 128B.
// ---------------------------------------------------------------------------
__global__ void quant_rows_kernel(const float* __restrict__ x) {
    int row = blockIdx.x;
    int t = threadIdx.x;
    const float4* xr = reinterpret_cast<const float4*>(x + (size_t)row * K_DIM);
    float4 v[4];
    float amax = 0.0f;
#pragma unroll
    for (int i = 0; i < 4; i++) {
        v[i] = xr[t * 4 + i];
        amax = fmaxf(amax, fabsf(v[i].x));
        amax = fmaxf(amax, fabsf(v[i].y));
        amax = fmaxf(amax, fabsf(v[i].z));
        amax = fmaxf(amax, fabsf(v[i].w));
    }
    __shared__ float red[8];
    __shared__ float s_scale;
#pragma unroll
    for (int o = 16; o > 0; o >>= 1)
        amax = fmaxf(amax, __shfl_xor_sync(0xffffffffu, amax, o));
    if ((t & 31) == 0) red[t >> 5] = amax;
    __syncthreads();
    if (t == 0) {
        float m = red[0];
#pragma unroll
        for (int i = 1; i < 8; i++) m = fmaxf(m, red[i]);
        float sc = m / 127.0f;
        s_scale = sc;
        g_sx[row] = sc;
    }
    __syncthreads();
    float scale = s_scale;

    union { __nv_bfloat16 h[16]; int4 i4[2]; } q;
#pragma unroll
    for (int i = 0; i < 4; i++) {
        q.h[i * 4 + 0] = __float2bfloat16_rn((float)__float2int_rn(v[i].x / scale));
        q.h[i * 4 + 1] = __float2bfloat16_rn((float)__float2int_rn(v[i].y / scale));
        q.h[i * 4 + 2] = __float2bfloat16_rn((float)__float2int_rn(v[i].z / scale));
        q.h[i * 4 + 3] = __float2bfloat16_rn((float)__float2int_rn(v[i].w / scale));
    }
    int tm = row >> 7, lrow = row & 127;
    int kt = t >> 2;
    int ch0 = (t & 3) * 2;
    char* blk = (char*)g_qa + (((size_t)tm * NKT + kt) << 14) + (size_t)lrow * 128;
    *reinterpret_cast<int4*>(blk + (((ch0)     ^ (lrow & 7)) << 4)) = q.i4[0];
    *reinterpret_cast<int4*>(blk + (((ch0 + 1) ^ (lrow & 7)) << 4)) = q.i4[1];
}

// ---------------------------------------------------------------------------
// Kernel 2: int32 weights -> bf16 (exact), tile-major swizzled image:
// g_wb blocks [tn][kt] of 128 rows x 128 bytes (BN=128 tiling).
// ---------------------------------------------------------------------------
__global__ void convert_w_kernel(const int* __restrict__ w) {
    int n = blockIdx.x;
    int t = threadIdx.x;
    const int4* wr = reinterpret_cast<const int4*>(w + (size_t)n * K_DIM);
    union { __nv_bfloat16 h[16]; int4 i4[2]; } q;
#pragma unroll
    for (int i = 0; i < 4; i++) {
        int4 v = wr[t * 4 + i];
        q.h[i * 4 + 0] = __float2bfloat16_rn((float)v.x);
        q.h[i * 4 + 1] = __float2bfloat16_rn((float)v.y);
        q.h[i * 4 + 2] = __float2bfloat16_rn((float)v.z);
        q.h[i * 4 + 3] = __float2bfloat16_rn((float)v.w);
    }
    int tn = n >> 7, lrow = n & 127;
    int kt = t >> 2;
    int ch0 = (t & 3) * 2;
    char* blk = (char*)g_wb + (((size_t)tn * NKT + kt) << 14) + (size_t)lrow * 128;
    *reinterpret_cast<int4*>(blk + (((ch0)     ^ (lrow & 7)) << 4)) = q.i4[0];
    *reinterpret_cast<int4*>(blk + (((ch0 + 1) ^ (lrow & 7)) << 4)) = q.i4[1];
}

// ---------------------------------------------------------------------------
// Kernel 3: persistent bf16 HMMA GEMM. CTA tile 128x128, 8 warps (32x64 warp
// tiles), NS=3 bulk-copy mbarrier ring that runs CONTINUOUSLY across tiles;
// 2 CTAs/SM. Epilogue overlaps the next tile's loads.
// ---------------------------------------------------------------------------
__device__ __forceinline__ uint32_t smem_u32(const void* p) {
    uint32_t a;
    asm("{ .reg .u64 t; cvta.to.shared.u64 t, %1; cvt.u32.u64 %0, t; }" : "=r"(a) : "l"(p));
    return a;
}
__device__ __forceinline__ void mbar_init(uint32_t a, uint32_t c) {
    asm volatile("mbarrier.init.shared.b64 [%0], %1;" :: "r"(a), "r"(c) : "memory");
}
__device__ __forceinline__ void mbar_expect_tx(uint32_t a, uint32_t tx) {
    asm volatile("mbarrier.arrive.expect_tx.shared::cta.b64 _, [%0], %1;"
                 :: "r"(a), "r"(tx) : "memory");
}
__device__ __forceinline__ void bulk_g2s(uint32_t dst, const void* src, uint32_t bytes,
                                         uint32_t mbar) {
    asm volatile(
        "cp.async.bulk.shared::cta.global.mbarrier::complete_tx::bytes [%0], [%1], %2, [%3];"
        :: "r"(dst), "l"(src), "r"(bytes), "r"(mbar) : "memory");
}
__device__ __forceinline__ void mbar_wait(uint32_t a, uint32_t ph) {
    asm volatile(
        "{\n .reg .pred P;\n"
        "WL_%=:\n"
        " mbarrier.try_wait.parity.acquire.cta.shared::cta.b64 P, [%0], %1;\n"
        " @P bra.uni WD_%=;\n"
        " bra.uni WL_%=;\n"
        "WD_%=:\n}" :: "r"(a), "r"(ph) : "memory");
}
__device__ __forceinline__ void ldm_x4(uint32_t& r0, uint32_t& r1, uint32_t& r2,
                                       uint32_t& r3, uint32_t addr) {
    asm volatile("ldmatrix.sync.aligned.m8n8.x4.shared.b16 {%0,%1,%2,%3}, [%4];"
                 : "=r"(r0), "=r"(r1), "=r"(r2), "=r"(r3) : "r"(addr));
}
__device__ __forceinline__ void tile_decode(int tile, int& tm, int& tn) {
    int grp = tile >> 10;                 // 1024 tiles per group (8 tm x 128 tn)
    int rem = tile & 1023;
    tm = grp * 8 + (rem & 7);
    tn = rem >> 3;
}

__global__ __launch_bounds__(256, 2) void gemm_hmma_kernel(const float* __restrict__ wscale,
                                                           const float* __restrict__ bias,
                                                           float* __restrict__ out) {
    extern __shared__ char smem[];
    uint32_t raw = smem_u32(smem);
    uint32_t sbase = (raw + 1023u) & ~1023u;
    uint32_t fullb = sbase + NS * STG;            // NS x 8B

    const int t = threadIdx.x;
    const int wid = t >> 5;
    const int lane = t & 31;
    const int warpM = wid & 3;                    // 4 warps along M (32 rows each)
    const int warpN = wid >> 2;                   // 2 warps along N (64 cols each)

    const int my_count = (TILES_TOTAL - (int)blockIdx.x + (int)gridDim.x - 1) / (int)gridDim.x;
    const int g_end = my_count * NKT;

    if (t == 0) {
#pragma unroll
        for (int s = 0; s < NS; s++) mbar_init(fullb + 8 * s, 1);
    }
    __syncthreads();

    // issue loads for global step gg (t0 only)
    auto issue = [&](int gg) {
        int ord = gg >> 6;
        int ktl = gg & (NKT - 1);
        int tile = (int)blockIdx.x + ord * (int)gridDim.x;
        int tm2, tn2;
        tile_decode(tile, tm2, tn2);
        int buf = gg % NS;
        uint32_t mb = fullb + 8 * buf;
        mbar_expect_tx(mb, STG);
        bulk_g2s(sbase + buf * STG,
                 (const char*)g_qa + (((size_t)tm2 * NKT + ktl) << 14), STG_A, mb);
        bulk_g2s(sbase + buf * STG + STG_A,
                 (const char*)g_wb + (((size_t)tn2 * NKT + ktl) << 14), STG_B, mb);
    };

    if (t == 0) {
        issue(0);
        if (g_end > 1) issue(1);
    }

    const int seg = lane >> 3;
    const int lrow = lane & 7;
    const int a_rb = warpM * 32 + (seg & 1) * 8 + lrow;    // + mf*16
    const int b_rb = warpN * 64 + (seg & 1) * 8 + lrow;    // + nf2*16
    const int cseg = seg >> 1;
    const int tig = lane & 3;
    const int gID = lane >> 2;

    int s = 0, ph = 0, g = 0;

    for (int ord = 0; ord < my_count; ord++) {
        int tile = (int)blockIdx.x + ord * (int)gridDim.x;
        int tm, tn;
        tile_decode(tile, tm, tn);

        float acc[2][8][4];
#pragma unroll
        for (int mf = 0; mf < 2; mf++)
#pragma unroll
            for (int nf = 0; nf < 8; nf++)
#pragma unroll
                for (int i = 0; i < 4; i++) acc[mf][nf][i] = 0.0f;

        for (int kt = 0; kt < NKT; kt++, g++) {
            // top-of-loop issue for step g+2: its buffer was freed by the
            // __syncthreads at the end of step g-1.
            if (t == 0 && g + 2 < g_end) issue(g + 2);

            mbar_wait(fullb + 8 * s, ph);

            uint32_t sA = sbase + s * STG;
            uint32_t sB = sA + STG_A;

#pragma unroll
            for (int ks = 0; ks < 4; ks++) {
                const int chunk = cseg + 2 * ks;
                uint32_t a[2][4], b[8][2];
#pragma unroll
                for (int mf = 0; mf < 2; mf++) {
                    int r = a_rb + mf * 16;
                    ldm_x4(a[mf][0], a[mf][1], a[mf][2], a[mf][3],
                           sA + r * 128 + ((chunk ^ (r & 7)) << 4));
                }
#pragma unroll
                for (int nf2 = 0; nf2 < 4; nf2++) {
                    int r = b_rb + nf2 * 16;
                    uint32_t r0, r1, r2, r3;
                    ldm_x4(r0, r1, r2, r3, sB + r * 128 + ((chunk ^ (r & 7)) << 4));
                    b[nf2 * 2][0] = r0; b[nf2 * 2][1] = r2;
                    b[nf2 * 2 + 1][0] = r1; b[nf2 * 2 + 1][1] = r3;
                }
#pragma unroll
                for (int mf = 0; mf < 2; mf++)
#pragma unroll
                    for (int nf = 0; nf < 8; nf++)
                        asm volatile(
                            "mma.sync.aligned.m16n8k16.row.col.f32.bf16.bf16.f32 "
                            "{%0,%1,%2,%3}, {%4,%5,%6,%7}, {%8,%9}, {%0,%1,%2,%3};\n"
                            : "+f"(acc[mf][nf][0]), "+f"(acc[mf][nf][1]),
                              "+f"(acc[mf][nf][2]), "+f"(acc[mf][nf][3])
                            : "r"(a[mf][0]), "r"(a[mf][1]), "r"(a[mf][2]), "r"(a[mf][3]),
                              "r"(b[nf][0]), "r"(b[nf][1]));
            }

            __syncthreads();
            if (++s == NS) { s = 0; ph ^= 1; }
        }

        // epilogue: dequant + bias (next tile's loads are in flight meanwhile)
#pragma unroll
        for (int mf = 0; mf < 2; mf++) {
            int r0 = tm * BM + warpM * 32 + mf * 16 + gID;
            float sx0 = g_sx[r0];
            float sx1 = g_sx[r0 + 8];
            float* o0 = out + (size_t)r0 * N_DIM + tn * BN;
            float* o1 = o0 + (size_t)8 * N_DIM;
#pragma unroll
            for (int nf = 0; nf < 8; nf++) {
                int c = warpN * 64 + nf * 8 + tig * 2;
                float w0 = __ldg(wscale + tn * BN + c);
                float w1 = __ldg(wscale + tn * BN + c + 1);
                float b0 = __ldg(bias + tn * BN + c);
                float b1 = __ldg(bias + tn * BN + c + 1);
                float2 v0, v1;
                v0.x = acc[mf][nf][0] * sx0 * w0 + b0;
                v0.y = acc[mf][nf][1] * sx0 * w1 + b1;
                v1.x = acc[mf][nf][2] * sx1 * w0 + b0;
                v1.y = acc[mf][nf][3] * sx1 * w1 + b1;
                *(float2*)(o0 + c) = v0;
                *(float2*)(o1 + c) = v1;
            }
        }
    }
}

// ---------------------------------------------------------------------------
extern "C" void kernel_launch(void* const* d_in, const int* in_sizes, int n_in,
                              void* d_out, int out_size) {
    (void)in_sizes; (void)n_in; (void)out_size;
    const float* x      = (const float*)d_in[0];
    const int*   wq     = (const int*)d_in[1];
    const float* wscale = (const float*)d_in[2];
    const float* bias   = (const float*)d_in[3];
    float* out = (float*)d_out;

    quant_rows_kernel<<<M_DIM, 256>>>(x);
    convert_w_kernel<<<N_DIM, 256>>>(wq);

    int nsm = 148;
    cudaDeviceGetAttribute(&nsm, cudaDevAttrMultiProcessorCount, 0);
    int grid = nsm * 2;                               // persistent: 2 CTAs/SM
    if (grid > TILES_TOTAL) grid = TILES_TOTAL;

    cudaFuncSetAttribute(gemm_hmma_kernel, cudaFuncAttributeMaxDynamicSharedMemorySize,
                         SMEM_TOTAL);
    gemm_hmma_kernel<<<grid, 256, SMEM_TOTAL>>>(wscale, bias, out);
}

// round 10
// speedup vs baseline: 1.0597x; 1.0597x over previous
#include <cuda_runtime.h>
#include <cuda_bf16.h>
#include <cstdint>

#define M_DIM 8192
#define K_DIM 4096
#define N_DIM 16384

#define BM 128
#define BN 128
#define BKE 64                     // K elements per stage (bf16) = 128B rows
#define NKT (K_DIM / BKE)          // 64
#define NS 3
#define STG_A (BM * 128)           // 16384 bytes
#define STG_B (BN * 128)           // 16384 bytes
#define STG (STG_A + STG_B)        // 32768
#define SMEM_TOTAL (NS * STG + 1024 + 128)

// Tiled, pre-swizzled bf16 operand images (device globals; allocation-free rule)
static __device__ __align__(128) __nv_bfloat16 g_qa[(size_t)M_DIM * K_DIM];  // 64 MB
static __device__ __align__(128) __nv_bfloat16 g_wb[(size_t)N_DIM * K_DIM];  // 128 MB
static __device__ float g_sx[M_DIM];

// ---------------------------------------------------------------------------
// Kernel 1: per-row absmax + int8 quantization -> bf16 (exact for |q|<=127),
// tile-major swizzled image: g_qa blocks [tm][kt], 128 rows x 128B.
// ---------------------------------------------------------------------------
__global__ void quant_rows_kernel(const float* __restrict__ x) {
    int row = blockIdx.x;
    int t = threadIdx.x;
    const float4* xr = reinterpret_cast<const float4*>(x + (size_t)row * K_DIM);
    float4 v[4];
    float amax = 0.0f;
#pragma unroll
    for (int i = 0; i < 4; i++) {
        v[i] = xr[t * 4 + i];
        amax = fmaxf(amax, fabsf(v[i].x));
        amax = fmaxf(amax, fabsf(v[i].y));
        amax = fmaxf(amax, fabsf(v[i].z));
        amax = fmaxf(amax, fabsf(v[i].w));
    }
    __shared__ float red[8];
    __shared__ float s_scale;
#pragma unroll
    for (int o = 16; o > 0; o >>= 1)
        amax = fmaxf(amax, __shfl_xor_sync(0xffffffffu, amax, o));
    if ((t & 31) == 0) red[t >> 5] = amax;
    __syncthreads();
    if (t == 0) {
        float m = red[0];
#pragma unroll
        for (int i = 1; i < 8; i++) m = fmaxf(m, red[i]);
        float sc = m / 127.0f;
        s_scale = sc;
        g_sx[row] = sc;
    }
    __syncthreads();
    float scale = s_scale;

    union { __nv_bfloat16 h[16]; int4 i4[2]; } q;
#pragma unroll
    for (int i = 0; i < 4; i++) {
        q.h[i * 4 + 0] = __float2bfloat16_rn((float)__float2int_rn(v[i].x / scale));
        q.h[i * 4 + 1] = __float2bfloat16_rn((float)__float2int_rn(v[i].y / scale));
        q.h[i * 4 + 2] = __float2bfloat16_rn((float)__float2int_rn(v[i].z / scale));
        q.h[i * 4 + 3] = __float2bfloat16_rn((float)__float2int_rn(v[i].w / scale));
    }
    int tm = row >> 7, lrow = row & 127;
    int kt = t >> 2;
    int ch0 = (t & 3) * 2;
    char* blk = (char*)g_qa + (((size_t)tm * NKT + kt) << 14) + (size_t)lrow * 128;
    *reinterpret_cast<int4*>(blk + (((ch0)     ^ (lrow & 7)) << 4)) = q.i4[0];
    *reinterpret_cast<int4*>(blk + (((ch0 + 1) ^ (lrow & 7)) << 4)) = q.i4[1];
}

// ---------------------------------------------------------------------------
// Kernel 2: int32 weights -> bf16 (exact), tile-major swizzled image:
// g_wb blocks [tn][kt] of 128 rows x 128 bytes (BN=128 tiling).
// ---------------------------------------------------------------------------
__global__ void convert_w_kernel(const int* __restrict__ w) {
    int n = blockIdx.x;
    int t = threadIdx.x;
    const int4* wr = reinterpret_cast<const int4*>(w + (size_t)n * K_DIM);
    union { __nv_bfloat16 h[16]; int4 i4[2]; } q;
#pragma unroll
    for (int i = 0; i < 4; i++) {
        int4 v = wr[t * 4 + i];
        q.h[i * 4 + 0] = __float2bfloat16_rn((float)v.x);
        q.h[i * 4 + 1] = __float2bfloat16_rn((float)v.y);
        q.h[i * 4 + 2] = __float2bfloat16_rn((float)v.z);
        q.h[i * 4 + 3] = __float2bfloat16_rn((float)v.w);
    }
    int tn = n >> 7, lrow = n & 127;
    int kt = t >> 2;
    int ch0 = (t & 3) * 2;
    char* blk = (char*)g_wb + (((size_t)tn * NKT + kt) << 14) + (size_t)lrow * 128;
    *reinterpret_cast<int4*>(blk + (((ch0)     ^ (lrow & 7)) << 4)) = q.i4[0];
    *reinterpret_cast<int4*>(blk + (((ch0 + 1) ^ (lrow & 7)) << 4)) = q.i4[1];
}

// ---------------------------------------------------------------------------
// Kernel 3: bf16 HMMA GEMM, CTA tile 128x128, 8 warps (warp tile 32x64),
// NS=3 bulk-copy mbarrier pipeline (top-of-loop issue), 2 CTAs/SM.
// ---------------------------------------------------------------------------
__device__ __forceinline__ uint32_t smem_u32(const void* p) {
    uint32_t a;
    asm("{ .reg .u64 t; cvta.to.shared.u64 t, %1; cvt.u32.u64 %0, t; }" : "=r"(a) : "l"(p));
    return a;
}
__device__ __forceinline__ void mbar_init(uint32_t a, uint32_t c) {
    asm volatile("mbarrier.init.shared.b64 [%0], %1;" :: "r"(a), "r"(c) : "memory");
}
__device__ __forceinline__ void mbar_expect_tx(uint32_t a, uint32_t tx) {
    asm volatile("mbarrier.arrive.expect_tx.shared::cta.b64 _, [%0], %1;"
                 :: "r"(a), "r"(tx) : "memory");
}
__device__ __forceinline__ void bulk_g2s(uint32_t dst, const void* src, uint32_t bytes,
                                         uint32_t mbar) {
    asm volatile(
        "cp.async.bulk.shared::cta.global.mbarrier::complete_tx::bytes [%0], [%1], %2, [%3];"
        :: "r"(dst), "l"(src), "r"(bytes), "r"(mbar) : "memory");
}
__device__ __forceinline__ void mbar_wait(uint32_t a, uint32_t ph) {
    asm volatile(
        "{\n .reg .pred P;\n"
        "WL_%=:\n"
        " mbarrier.try_wait.parity.acquire.cta.shared::cta.b64 P, [%0], %1;\n"
        " @P bra.uni WD_%=;\n"
        " bra.uni WL_%=;\n"
        "WD_%=:\n}" :: "r"(a), "r"(ph) : "memory");
}
__device__ __forceinline__ void ldm_x4(uint32_t& r0, uint32_t& r1, uint32_t& r2,
                                       uint32_t& r3, uint32_t addr) {
    asm volatile("ldmatrix.sync.aligned.m8n8.x4.shared.b16 {%0,%1,%2,%3}, [%4];"
                 : "=r"(r0), "=r"(r1), "=r"(r2), "=r"(r3) : "r"(addr));
}

__global__ __launch_bounds__(256, 2) void gemm_hmma_kernel(const float* __restrict__ wscale,
                                                           const float* __restrict__ bias,
                                                           float* __restrict__ out) {
    extern __shared__ char smem[];
    uint32_t raw = smem_u32(smem);
    uint32_t sbase = (raw + 1023u) & ~1023u;
    uint32_t fullb = sbase + NS * STG;            // NS x 8B

    const int t = threadIdx.x;
    const int wid = t >> 5;
    const int lane = t & 31;
    const int warpM = wid & 3;                    // 4 warps along M (32 rows each)
    const int warpN = wid >> 2;                   // 2 warps along N (64 cols each)

    // tile decode with L2 group swizzle: tiles_m=64, tiles_n=128, GM=16
    // (16 tm per group halves B DRAM refetch vs GM=8: B swept 4x not 8x)
    int gid = blockIdx.x;
    int grp = gid >> 11;                          // / (16*128)
    int rem = gid & 2047;
    int tm = grp * 16 + (rem & 15);
    int tn = rem >> 4;

    const char* gA = (const char*)g_qa + ((size_t)tm * NKT << 14);
    const char* gB = (const char*)g_wb + ((size_t)tn * NKT << 14);

    if (t == 0) {
#pragma unroll
        for (int s = 0; s < NS; s++) mbar_init(fullb + 8 * s, 1);
    }
    __syncthreads();

    auto issue = [&](int buf, int kt) {
        uint32_t mb = fullb + 8 * buf;
        mbar_expect_tx(mb, STG);
        bulk_g2s(sbase + buf * STG,         gA + ((size_t)kt << 14), STG_A, mb);
        bulk_g2s(sbase + buf * STG + STG_A, gB + ((size_t)kt << 14), STG_B, mb);
    };

    if (t == 0) {
        issue(0, 0);
        issue(1, 1);
    }

    float acc[2][8][4];
#pragma unroll
    for (int mf = 0; mf < 2; mf++)
#pragma unroll
        for (int nf = 0; nf < 8; nf++)
#pragma unroll
            for (int i = 0; i < 4; i++) acc[mf][nf][i] = 0.0f;

    const int seg = lane >> 3;
    const int lrow = lane & 7;
    const int a_rb = warpM * 32 + (seg & 1) * 8 + lrow;    // + mf*16
    const int b_rb = warpN * 64 + (seg & 1) * 8 + lrow;    // + nf2*16
    const int cseg = seg >> 1;

    int s = 0, ph = 0;
    for (int kt = 0; kt < NKT; kt++) {
        // top-of-loop issue for kt+2: its buffer was freed by the
        // __syncthreads at the end of iteration kt-1 (unused yet for kt<1).
        if (t == 0 && kt + 2 < NKT) {
            int buf = s + 2;
            if (buf >= NS) buf -= NS;
            issue(buf, kt + 2);
        }

        mbar_wait(fullb + 8 * s, ph);

        uint32_t sA = sbase + s * STG;
        uint32_t sB = sA + STG_A;

#pragma unroll
        for (int ks = 0; ks < 4; ks++) {
            const int chunk = cseg + 2 * ks;
            uint32_t a[2][4], b[8][2];
#pragma unroll
            for (int mf = 0; mf < 2; mf++) {
                int r = a_rb + mf * 16;
                ldm_x4(a[mf][0], a[mf][1], a[mf][2], a[mf][3],
                       sA + r * 128 + ((chunk ^ (r & 7)) << 4));
            }
#pragma unroll
            for (int nf2 = 0; nf2 < 4; nf2++) {
                int r = b_rb + nf2 * 16;
                uint32_t r0, r1, r2, r3;
                ldm_x4(r0, r1, r2, r3, sB + r * 128 + ((chunk ^ (r & 7)) << 4));
                b[nf2 * 2][0] = r0; b[nf2 * 2][1] = r2;
                b[nf2 * 2 + 1][0] = r1; b[nf2 * 2 + 1][1] = r3;
            }
#pragma unroll
            for (int mf = 0; mf < 2; mf++)
#pragma unroll
                for (int nf = 0; nf < 8; nf++)
                    asm volatile(
                        "mma.sync.aligned.m16n8k16.row.col.f32.bf16.bf16.f32 "
                        "{%0,%1,%2,%3}, {%4,%5,%6,%7}, {%8,%9}, {%0,%1,%2,%3};\n"
                        : "+f"(acc[mf][nf][0]), "+f"(acc[mf][nf][1]),
                          "+f"(acc[mf][nf][2]), "+f"(acc[mf][nf][3])
                        : "r"(a[mf][0]), "r"(a[mf][1]), "r"(a[mf][2]), "r"(a[mf][3]),
                          "r"(b[nf][0]), "r"(b[nf][1]));
        }

        __syncthreads();
        if (++s == NS) { s = 0; ph ^= 1; }
    }

    // epilogue: dequant + bias
    const int tig = lane & 3;
    const int gID = lane >> 2;
#pragma unroll
    for (int mf = 0; mf < 2; mf++) {
        int r0 = tm * BM + warpM * 32 + mf * 16 + gID;
        float sx0 = g_sx[r0];
        float sx1 = g_sx[r0 + 8];
        float* o0 = out + (size_t)r0 * N_DIM + tn * BN;
        float* o1 = o0 + (size_t)8 * N_DIM;
#pragma unroll
        for (int nf = 0; nf < 8; nf++) {
            int c = warpN * 64 + nf * 8 + tig * 2;
            float w0 = __ldg(wscale + tn * BN + c);
            float w1 = __ldg(wscale + tn * BN + c + 1);
            float b0 = __ldg(bias + tn * BN + c);
            float b1 = __ldg(bias + tn * BN + c + 1);
            float2 v0, v1;
            v0.x = acc[mf][nf][0] * sx0 * w0 + b0;
            v0.y = acc[mf][nf][1] * sx0 * w1 + b1;
            v1.x = acc[mf][nf][2] * sx1 * w0 + b0;
            v1.y = acc[mf][nf][3] * sx1 * w1 + b1;
            *(float2*)(o0 + c) = v0;
            *(float2*)(o1 + c) = v1;
        }
    }
}

// ---------------------------------------------------------------------------
extern "C" void kernel_launch(void* const* d_in, const int* in_sizes, int n_in,
                              void* d_out, int out_size) {
    (void)in_sizes; (void)n_in; (void)out_size;
    const float* x      = (const float*)d_in[0];
    const int*   wq     = (const int*)d_in[1];
    const float* wscale = (const float*)d_in[2];
    const float* bias   = (const float*)d_in[3];
    float* out = (float*)d_out;

    quant_rows_kernel<<<M_DIM, 256>>>(x);
    convert_w_kernel<<<N_DIM, 256>>>(wq);

    cudaFuncSetAttribute(gemm_hmma_kernel, cudaFuncAttributeMaxDynamicSharedMemorySize,
                         SMEM_TOTAL);
    int gemm_blocks = (M_DIM / BM) * (N_DIM / BN);   // 8192
    gemm_hmma_kernel<<<gemm_blocks, 256, SMEM_TOTAL>>>(wscale, bias, out);
}